// round 14
// baseline (speedup 1.0000x reference)
#include <cuda_runtime.h>
#include <cuda_fp16.h>
#include <cstdint>

#define NT    16384
#define DIM   2048
#define NE    64
#define TT    128            // tokens per CTA
#define KCH   128            // k per smem chunk
#define NCHK  (DIM / KCH)    // 16
#define KS_PER_CH 8          // k16 steps per chunk
#define NKS   (DIM / 16)     // 128 total k16 steps
#define LSTR  66
#define GAP_THRESH 1e-4f

// smem w-plane layout: [prod][ks][n][48B rows]  (round-4 exact)
#define KSOFF 3104
#define POFF  (8 * KSOFF)          // 24832
#define SMEM_TOTAL (2 * POFF)      // 49664 (logits 128*66*4=33792 reused)

__device__ __forceinline__ uint32_t smem_u32(const void* p) {
    uint32_t a;
    asm("{ .reg .u64 t; cvta.to.shared.u64 t, %1; cvt.u32.u64 %0, t; }" : "=r"(a) : "l"(p));
    return a;
}

// split float2 into fp16 high + fp16 residual (packed half2 as u32)
__device__ __forceinline__ void split2(float2 v, uint32_t& h, uint32_t& m) {
    __half2 hh = __float22half2_rn(v);
    float2 hf = __half22float2(hh);
    __half2 mm = __floats2half2_rn(v.x - hf.x, v.y - hf.y);
    h = *reinterpret_cast<uint32_t*>(&hh);
    m = *reinterpret_cast<uint32_t*>(&mm);
}

__device__ __forceinline__ void ldm4(uint32_t addr, uint32_t& r0, uint32_t& r1,
                                     uint32_t& r2, uint32_t& r3) {
    asm volatile("ldmatrix.sync.aligned.m8n8.x4.shared.b16 {%0,%1,%2,%3}, [%4];"
                 : "=r"(r0), "=r"(r1), "=r"(r2), "=r"(r3) : "r"(addr));
}

__device__ __forceinline__ void mma16816(float* c, uint32_t a0, uint32_t a1,
                                         uint32_t a2, uint32_t a3,
                                         uint32_t b0, uint32_t b1) {
    asm volatile("mma.sync.aligned.m16n8k16.row.col.f32.f16.f16.f32 "
                 "{%0,%1,%2,%3}, {%4,%5,%6,%7}, {%8,%9}, {%0,%1,%2,%3};"
                 : "+f"(c[0]), "+f"(c[1]), "+f"(c[2]), "+f"(c[3])
                 : "r"(a0), "r"(a1), "r"(a2), "r"(a3), "r"(b0), "r"(b1));
}

// ---------------- Kernel: R4 HMMA fast path + inline fixup ----------------
__global__ __launch_bounds__(512, 1)
void router_hmma(const float* __restrict__ x, const float* __restrict__ w,
                 float* __restrict__ out)
{
    extern __shared__ __align__(16) char smem[];
    const uint32_t wsu = smem_u32(smem);

    __shared__ int   s_cnt;
    __shared__ int   s_list[TT];
    __shared__ float s_part[8][64];
    __shared__ float s_lg[66];

    const int tid  = threadIdx.x;
    const int lane = tid & 31;
    const int wp   = tid >> 5;           // 0..15
    const int tok0 = blockIdx.x * TT;

    if (tid == 0) s_cnt = 0;

    const int qrow  = lane >> 2;
    const int qk    = (lane & 3) * 2;
    const int rbase = 16 * (wp & 7);
    const int jb    = (wp >> 3) * 4;

    const int lm_m = lane >> 3, lm_i = lane & 7;
    const uint32_t lmoff = (uint32_t)((8 * (lm_m >> 1) + lm_i) * 48 + (lm_m & 1) * 16);

    const float* xa = x + (size_t)(tok0 + rbase + qrow) * DIM + qk;

    float acc[4][4];
#pragma unroll
    for (int j = 0; j < 4; j++)
#pragma unroll
        for (int q = 0; q < 4; q++) acc[j][q] = 0.0f;

    float2 pa[2][4];
    auto loadA = [&](int g, int s) {
        const float* p = xa + 16 * g;
        pa[s][0] = *reinterpret_cast<const float2*>(p);
        pa[s][1] = *reinterpret_cast<const float2*>(p + 8);
        pa[s][2] = *reinterpret_cast<const float2*>(p + 8 * DIM);
        pa[s][3] = *reinterpret_cast<const float2*>(p + 8 * DIM + 8);
    };
    loadA(0, 0);
    loadA(1, 1);

    float4 wr[4];
    auto loadW = [&](int ch) {
#pragma unroll
        for (int l = 0; l < 4; l++) {
            int f = tid + 512 * l;
            int n = f >> 5, q = f & 31;
            wr[l] = *reinterpret_cast<const float4*>(
                w + (size_t)n * DIM + ch * KCH + q * 4);
        }
    };
    loadW(0);

    for (int ch = 0; ch < NCHK; ch++) {
        __syncthreads();
#pragma unroll
        for (int l = 0; l < 4; l++) {
            int f = tid + 512 * l;
            int n = f >> 5, q = f & 31;
            uint32_t h01, m01, h23, m23;
            split2(make_float2(wr[l].x * 256.0f, wr[l].y * 256.0f), h01, m01);
            split2(make_float2(wr[l].z * 256.0f, wr[l].w * 256.0f), h23, m23);
            uint32_t off = (uint32_t)((q >> 2) * KSOFF + n * 48 + (q & 3) * 8);
            *reinterpret_cast<uint2*>(smem + off)        = make_uint2(h01, h23);
            *reinterpret_cast<uint2*>(smem + POFF + off) = make_uint2(m01, m23);
        }
        __syncthreads();
        if (ch + 1 < NCHK) loadW(ch + 1);

#pragma unroll
        for (int ks = 0; ks < KS_PER_CH; ks++) {
            const int g = ch * KS_PER_CH + ks;
            const int s = g & 1;

            uint32_t ah[4], am[4];
            split2(pa[s][0], ah[0], am[0]);
            split2(pa[s][2], ah[1], am[1]);
            split2(pa[s][1], ah[2], am[2]);
            split2(pa[s][3], ah[3], am[3]);
            if (g + 2 < NKS) loadA(g + 2, s);

            const uint32_t bh_base = wsu + (uint32_t)(ks * KSOFF) + lmoff;
            uint32_t bh[8], bm[8];
            ldm4(bh_base + (jb + 0) * 384, bh[0], bh[1], bh[2], bh[3]);
            ldm4(bh_base + (jb + 2) * 384, bh[4], bh[5], bh[6], bh[7]);
#pragma unroll
            for (int j = 0; j < 4; j++)
                mma16816(acc[j], ah[0], ah[1], ah[2], ah[3], bh[2 * j], bh[2 * j + 1]);
#pragma unroll
            for (int j = 0; j < 4; j++)
                mma16816(acc[j], am[0], am[1], am[2], am[3], bh[2 * j], bh[2 * j + 1]);
            ldm4(bh_base + POFF + (jb + 0) * 384, bm[0], bm[1], bm[2], bm[3]);
            ldm4(bh_base + POFF + (jb + 2) * 384, bm[4], bm[5], bm[6], bm[7]);
#pragma unroll
            for (int j = 0; j < 4; j++)
                mma16816(acc[j], ah[0], ah[1], ah[2], ah[3], bm[2 * j], bm[2 * j + 1]);
        }
    }

    __syncthreads();
    float* ls = reinterpret_cast<float*>(smem);
    {
        const int r0 = rbase + qrow, r1 = r0 + 8;
        const int e00 = 32 * (wp >> 3) + qk;
#pragma unroll
        for (int j = 0; j < 4; j++) {
            int e = e00 + 8 * j;
            *reinterpret_cast<float2*>(ls + r0 * LSTR + e) =
                make_float2(acc[j][0] * 0.00390625f, acc[j][1] * 0.00390625f);
            *reinterpret_cast<float2*>(ls + r1 * LSTR + e) =
                make_float2(acc[j][2] * 0.00390625f, acc[j][3] * 0.00390625f);
        }
    }
    __syncthreads();

    float* outp = out;
    float* outi = out + (size_t)NT * 8;
    float* outa = out + (size_t)NT * 16;

    const int tbase = wp * 8;
#pragma unroll 1
    for (int tt = 0; tt < 8; tt++) {
        const int tok = tbase + tt;
        float2 v = *reinterpret_cast<const float2*>(ls + tok * LSTR + 2 * lane);

        float m = fmaxf(v.x, v.y);
#pragma unroll
        for (int o = 16; o > 0; o >>= 1)
            m = fmaxf(m, __shfl_xor_sync(0xffffffffu, m, o));

        float e0 = expf(v.x - m);
        float e1 = expf(v.y - m);
        float ssum = e0 + e1;
#pragma unroll
        for (int o = 16; o > 0; o >>= 1)
            ssum += __shfl_xor_sync(0xffffffffu, ssum, o);

        float inv = 1.0f / ssum;
        float p0 = e0 * inv, p1 = e1 * inv;

        const int gtok = tok0 + tok;
        *reinterpret_cast<float2*>(outa + (size_t)gtok * 64 + 2 * lane)
            = make_float2(p0, p1);

        // top-9 on LOGITS, track min adjacent gap
        float c0 = v.x, c1 = v.y;
        int i0 = 2 * lane, i1 = 2 * lane + 1;
        float tv = 0.0f, tsum = 0.0f, prevv = 0.0f, mingap = 1e30f;
        int ti = 0;
#pragma unroll
        for (int r = 0; r < 9; r++) {
            float bv; int bi;
            if (c0 > c1 || (c0 == c1 && i0 < i1)) { bv = c0; bi = i0; }
            else                                  { bv = c1; bi = i1; }
#pragma unroll
            for (int o = 16; o > 0; o >>= 1) {
                float ov = __shfl_xor_sync(0xffffffffu, bv, o);
                int   oi = __shfl_xor_sync(0xffffffffu, bi, o);
                if (ov > bv || (ov == bv && oi < bi)) { bv = ov; bi = oi; }
            }
            if (r > 0) mingap = fminf(mingap, prevv - bv);
            prevv = bv;
            if (r < 8) {
                float bp = expf(bv - m) * inv;
                tsum += bp;
                if (lane == r) { tv = bp; ti = bi; }
                if (bi == i0)      c0 = -1e30f;
                else if (bi == i1) c1 = -1e30f;
            }
        }
        if (lane < 8) {
            outp[(size_t)gtok * 8 + lane] = tv / (tsum + 1e-9f);
            outi[(size_t)gtok * 8 + lane] = (float)ti;
        }
        if (lane == 0 && mingap < GAP_THRESH) {
            int pos = atomicAdd(&s_cnt, 1);
            s_list[pos] = gtok;
        }
    }

    // ---- inline exact fp32 fixup for this CTA's flagged tokens ----
    __syncthreads();
    const int nfix = s_cnt;
    for (int i = 0; i < nfix; i++) {
        const int tok = s_list[i];
        const int e = tid & 63, kp = tid >> 6;        // 8 k-parts of 256
        const float* xr = x + (size_t)tok * DIM + kp * 256;
        const float* wr2 = w + (size_t)e * DIM + kp * 256;
        float s = 0.0f;
#pragma unroll 4
        for (int k = 0; k < 256; k += 4) {
            float4 xv = *reinterpret_cast<const float4*>(xr + k);
            float4 wv = *reinterpret_cast<const float4*>(wr2 + k);
            s = fmaf(xv.x, wv.x, s);
            s = fmaf(xv.y, wv.y, s);
            s = fmaf(xv.z, wv.z, s);
            s = fmaf(xv.w, wv.w, s);
        }
        s_part[kp][e] = s;
        __syncthreads();
        if (tid < 64) {
            float a = (s_part[0][tid] + s_part[1][tid]) + (s_part[2][tid] + s_part[3][tid]);
            float b = (s_part[4][tid] + s_part[5][tid]) + (s_part[6][tid] + s_part[7][tid]);
            s_lg[tid] = a + b;
        }
        __syncthreads();

        if (tid < 32) {
            float2 v = make_float2(s_lg[2 * lane], s_lg[2 * lane + 1]);

            float m = fmaxf(v.x, v.y);
#pragma unroll
            for (int o = 16; o > 0; o >>= 1)
                m = fmaxf(m, __shfl_xor_sync(0xffffffffu, m, o));

            float e0 = expf(v.x - m);
            float e1 = expf(v.y - m);
            float ssum = e0 + e1;
#pragma unroll
            for (int o = 16; o > 0; o >>= 1)
                ssum += __shfl_xor_sync(0xffffffffu, ssum, o);

            float inv = 1.0f / ssum;
            float p0 = e0 * inv, p1 = e1 * inv;

            *reinterpret_cast<float2*>(outa + (size_t)tok * 64 + 2 * lane)
                = make_float2(p0, p1);

            float c0 = p0, c1 = p1;
            int i0 = 2 * lane, i1 = 2 * lane + 1;
            float tv = 0.0f, tsum = 0.0f;
            int ti = 0;
#pragma unroll
            for (int r = 0; r < 8; r++) {
                float bv; int bi;
                if (c0 > c1 || (c0 == c1 && i0 < i1)) { bv = c0; bi = i0; }
                else                                  { bv = c1; bi = i1; }
#pragma unroll
                for (int o = 16; o > 0; o >>= 1) {
                    float ov = __shfl_xor_sync(0xffffffffu, bv, o);
                    int   oi = __shfl_xor_sync(0xffffffffu, bi, o);
                    if (ov > bv || (ov == bv && oi < bi)) { bv = ov; bi = oi; }
                }
                tsum += bv;
                if (lane == r) { tv = bv; ti = bi; }
                if (bi == i0)      c0 = -1.0f;
                else if (bi == i1) c1 = -1.0f;
            }
            if (lane < 8) {
                outp[(size_t)tok * 8 + lane] = tv / (tsum + 1e-9f);
                outi[(size_t)tok * 8 + lane] = (float)ti;
            }
        }
        __syncthreads();
    }
}

extern "C" void kernel_launch(void* const* d_in, const int* in_sizes, int n_in,
                              void* d_out, int out_size)
{
    (void)in_sizes; (void)n_in; (void)out_size;
    const float* x = (const float*)d_in[0];
    const float* w = (const float*)d_in[1];
    cudaFuncSetAttribute(router_hmma, cudaFuncAttributeMaxDynamicSharedMemorySize,
                         SMEM_TOTAL);
    router_hmma<<<NT / TT, 512, SMEM_TOTAL>>>(x, w, (float*)d_out);
}

// round 15
// speedup vs baseline: 1.6405x; 1.6405x over previous
#include <cuda_runtime.h>
#include <cuda_fp16.h>
#include <cstdint>

#define NT    16384
#define DIM   2048
#define NE    64
#define TT    128            // tokens per CTA
#define KCH   128            // k per smem chunk
#define NCHK  (DIM / KCH)    // 16
#define KS_PER_CH 8          // k16 steps per chunk
#define NKS   (DIM / 16)     // 128 total k16 steps
#define LSTR  66
#define GAP_THRESH 1e-4f     // logit-gap flag threshold
#define MAXFIX 1024

// smem w-plane layout: [prod][ks][n][48B rows]
#define KSOFF 3104
#define POFF  (8 * KSOFF)          // 24832
#define SMEM_TOTAL (2 * POFF)      // 49664 (logits 128*66*4=33792 reused)

__device__ int g_cnt;        // flag counter (self-resetting)
__device__ int g_cnt2;       // stable snapshot for fix kernel
__device__ int g_ctas_done;  // completion ticket
__device__ int g_list[MAXFIX];

__device__ __forceinline__ uint32_t smem_u32(const void* p) {
    uint32_t a;
    asm("{ .reg .u64 t; cvta.to.shared.u64 t, %1; cvt.u32.u64 %0, t; }" : "=r"(a) : "l"(p));
    return a;
}

// split float2 into fp16 high + fp16 residual (packed half2 as u32)
__device__ __forceinline__ void split2(float2 v, uint32_t& h, uint32_t& m) {
    __half2 hh = __float22half2_rn(v);
    float2 hf = __half22float2(hh);
    __half2 mm = __floats2half2_rn(v.x - hf.x, v.y - hf.y);
    h = *reinterpret_cast<uint32_t*>(&hh);
    m = *reinterpret_cast<uint32_t*>(&mm);
}

__device__ __forceinline__ void ldm4(uint32_t addr, uint32_t& r0, uint32_t& r1,
                                     uint32_t& r2, uint32_t& r3) {
    asm volatile("ldmatrix.sync.aligned.m8n8.x4.shared.b16 {%0,%1,%2,%3}, [%4];"
                 : "=r"(r0), "=r"(r1), "=r"(r2), "=r"(r3) : "r"(addr));
}

__device__ __forceinline__ void mma16816(float* c, uint32_t a0, uint32_t a1,
                                         uint32_t a2, uint32_t a3,
                                         uint32_t b0, uint32_t b1) {
    asm volatile("mma.sync.aligned.m16n8k16.row.col.f32.f16.f16.f32 "
                 "{%0,%1,%2,%3}, {%4,%5,%6,%7}, {%8,%9}, {%0,%1,%2,%3};"
                 : "+f"(c[0]), "+f"(c[1]), "+f"(c[2]), "+f"(c[3])
                 : "r"(a0), "r"(a1), "r"(a2), "r"(a3), "r"(b0), "r"(b1));
}

// ---------------- Kernel A: HMMA fast path (R4 verbatim) ----------------
__global__ __launch_bounds__(512, 1)
void router_hmma(const float* __restrict__ x, const float* __restrict__ w,
                 float* __restrict__ out)
{
    extern __shared__ __align__(16) char smem[];
    const uint32_t wsu = smem_u32(smem);

    const int tid  = threadIdx.x;
    const int lane = tid & 31;
    const int wp   = tid >> 5;           // 0..15
    const int tok0 = blockIdx.x * TT;

    const int qrow  = lane >> 2;
    const int qk    = (lane & 3) * 2;
    const int rbase = 16 * (wp & 7);
    const int jb    = (wp >> 3) * 4;

    const int lm_m = lane >> 3, lm_i = lane & 7;
    const uint32_t lmoff = (uint32_t)((8 * (lm_m >> 1) + lm_i) * 48 + (lm_m & 1) * 16);

    const float* xa = x + (size_t)(tok0 + rbase + qrow) * DIM + qk;

    float acc[4][4];
#pragma unroll
    for (int j = 0; j < 4; j++)
#pragma unroll
        for (int q = 0; q < 4; q++) acc[j][q] = 0.0f;

    float2 pa[2][4];
    auto loadA = [&](int g, int s) {
        const float* p = xa + 16 * g;
        pa[s][0] = *reinterpret_cast<const float2*>(p);
        pa[s][1] = *reinterpret_cast<const float2*>(p + 8);
        pa[s][2] = *reinterpret_cast<const float2*>(p + 8 * DIM);
        pa[s][3] = *reinterpret_cast<const float2*>(p + 8 * DIM + 8);
    };
    loadA(0, 0);
    loadA(1, 1);

    float4 wr[4];
    auto loadW = [&](int ch) {
#pragma unroll
        for (int l = 0; l < 4; l++) {
            int f = tid + 512 * l;
            int n = f >> 5, q = f & 31;
            wr[l] = *reinterpret_cast<const float4*>(
                w + (size_t)n * DIM + ch * KCH + q * 4);
        }
    };
    loadW(0);

    for (int ch = 0; ch < NCHK; ch++) {
        __syncthreads();
#pragma unroll
        for (int l = 0; l < 4; l++) {
            int f = tid + 512 * l;
            int n = f >> 5, q = f & 31;
            uint32_t h01, m01, h23, m23;
            split2(make_float2(wr[l].x * 256.0f, wr[l].y * 256.0f), h01, m01);
            split2(make_float2(wr[l].z * 256.0f, wr[l].w * 256.0f), h23, m23);
            uint32_t off = (uint32_t)((q >> 2) * KSOFF + n * 48 + (q & 3) * 8);
            *reinterpret_cast<uint2*>(smem + off)        = make_uint2(h01, h23);
            *reinterpret_cast<uint2*>(smem + POFF + off) = make_uint2(m01, m23);
        }
        __syncthreads();
        if (ch + 1 < NCHK) loadW(ch + 1);

#pragma unroll
        for (int ks = 0; ks < KS_PER_CH; ks++) {
            const int g = ch * KS_PER_CH + ks;
            const int s = g & 1;

            uint32_t ah[4], am[4];
            split2(pa[s][0], ah[0], am[0]);
            split2(pa[s][2], ah[1], am[1]);
            split2(pa[s][1], ah[2], am[2]);
            split2(pa[s][3], ah[3], am[3]);
            if (g + 2 < NKS) loadA(g + 2, s);

            const uint32_t bh_base = wsu + (uint32_t)(ks * KSOFF) + lmoff;
            uint32_t bh[8], bm[8];
            ldm4(bh_base + (jb + 0) * 384, bh[0], bh[1], bh[2], bh[3]);
            ldm4(bh_base + (jb + 2) * 384, bh[4], bh[5], bh[6], bh[7]);
#pragma unroll
            for (int j = 0; j < 4; j++)
                mma16816(acc[j], ah[0], ah[1], ah[2], ah[3], bh[2 * j], bh[2 * j + 1]);
#pragma unroll
            for (int j = 0; j < 4; j++)
                mma16816(acc[j], am[0], am[1], am[2], am[3], bh[2 * j], bh[2 * j + 1]);
            ldm4(bh_base + POFF + (jb + 0) * 384, bm[0], bm[1], bm[2], bm[3]);
            ldm4(bh_base + POFF + (jb + 2) * 384, bm[4], bm[5], bm[6], bm[7]);
#pragma unroll
            for (int j = 0; j < 4; j++)
                mma16816(acc[j], ah[0], ah[1], ah[2], ah[3], bm[2 * j], bm[2 * j + 1]);
        }
    }

    __syncthreads();
    float* ls = reinterpret_cast<float*>(smem);
    {
        const int r0 = rbase + qrow, r1 = r0 + 8;
        const int e00 = 32 * (wp >> 3) + qk;
#pragma unroll
        for (int j = 0; j < 4; j++) {
            int e = e00 + 8 * j;
            *reinterpret_cast<float2*>(ls + r0 * LSTR + e) =
                make_float2(acc[j][0] * 0.00390625f, acc[j][1] * 0.00390625f);
            *reinterpret_cast<float2*>(ls + r1 * LSTR + e) =
                make_float2(acc[j][2] * 0.00390625f, acc[j][3] * 0.00390625f);
        }
    }
    __syncthreads();

    float* outp = out;
    float* outi = out + (size_t)NT * 8;
    float* outa = out + (size_t)NT * 16;

    const int tbase = wp * 8;
#pragma unroll 1
    for (int tt = 0; tt < 8; tt++) {
        const int tok = tbase + tt;
        float2 v = *reinterpret_cast<const float2*>(ls + tok * LSTR + 2 * lane);

        float m = fmaxf(v.x, v.y);
#pragma unroll
        for (int o = 16; o > 0; o >>= 1)
            m = fmaxf(m, __shfl_xor_sync(0xffffffffu, m, o));

        float e0 = expf(v.x - m);
        float e1 = expf(v.y - m);
        float ssum = e0 + e1;
#pragma unroll
        for (int o = 16; o > 0; o >>= 1)
            ssum += __shfl_xor_sync(0xffffffffu, ssum, o);

        float inv = 1.0f / ssum;
        float p0 = e0 * inv, p1 = e1 * inv;

        const int gtok = tok0 + tok;
        *reinterpret_cast<float2*>(outa + (size_t)gtok * 64 + 2 * lane)
            = make_float2(p0, p1);

        // top-9 on LOGITS, track min adjacent gap
        float c0 = v.x, c1 = v.y;
        int i0 = 2 * lane, i1 = 2 * lane + 1;
        float tv = 0.0f, tsum = 0.0f, prevv = 0.0f, mingap = 1e30f;
        int ti = 0;
#pragma unroll
        for (int r = 0; r < 9; r++) {
            float bv; int bi;
            if (c0 > c1 || (c0 == c1 && i0 < i1)) { bv = c0; bi = i0; }
            else                                  { bv = c1; bi = i1; }
#pragma unroll
            for (int o = 16; o > 0; o >>= 1) {
                float ov = __shfl_xor_sync(0xffffffffu, bv, o);
                int   oi = __shfl_xor_sync(0xffffffffu, bi, o);
                if (ov > bv || (ov == bv && oi < bi)) { bv = ov; bi = oi; }
            }
            if (r > 0) mingap = fminf(mingap, prevv - bv);
            prevv = bv;
            if (r < 8) {
                float bp = expf(bv - m) * inv;   // bitwise == winning lane's prob
                tsum += bp;
                if (lane == r) { tv = bp; ti = bi; }
                if (bi == i0)      c0 = -1e30f;
                else if (bi == i1) c1 = -1e30f;
            }
        }
        if (lane < 8) {
            outp[(size_t)gtok * 8 + lane] = tv / (tsum + 1e-9f);
            outi[(size_t)gtok * 8 + lane] = (float)ti;
        }
        if (lane == 0 && mingap < GAP_THRESH) {
            int pos = atomicAdd(&g_cnt, 1);
            if (pos < MAXFIX) g_list[pos] = gtok;
        }
    }

    // ---- counter rotation: last CTA snapshots & resets (replaces zero_cnt) ----
    __syncthreads();
    if (tid == 0) {
        __threadfence();
        int t = atomicAdd(&g_ctas_done, 1);
        if (t == (int)gridDim.x - 1) {
            int c = atomicExch(&g_cnt, 0);
            g_cnt2 = (c > MAXFIX) ? MAXFIX : c;
            g_ctas_done = 0;
            __threadfence();
        }
    }
}

// ---------------- Kernel B: exact fp32 fixup for flagged tokens ----------------
__global__ __launch_bounds__(256)
void router_fix(const float* __restrict__ x, const float* __restrict__ w,
                float* __restrict__ out)
{
    const int n = g_cnt2;
    if ((int)blockIdx.x >= n) return;
    const int tok = g_list[blockIdx.x];

    __shared__ float part[4][64];
    __shared__ float lg[64 + 2];

    const int tid = threadIdx.x;
    const int e = tid & 63, kp = tid >> 6;       // 4 k-parts of 512

    const float* xr = x + (size_t)tok * DIM + kp * 512;
    const float* wr = w + (size_t)e * DIM + kp * 512;
    float s = 0.0f;
#pragma unroll 4
    for (int k = 0; k < 512; k += 4) {
        float4 xv = *reinterpret_cast<const float4*>(xr + k);
        float4 wv = *reinterpret_cast<const float4*>(wr + k);
        s = fmaf(xv.x, wv.x, s);
        s = fmaf(xv.y, wv.y, s);
        s = fmaf(xv.z, wv.z, s);
        s = fmaf(xv.w, wv.w, s);
    }
    part[kp][e] = s;
    __syncthreads();
    if (tid < 64)
        lg[tid] = (part[0][tid] + part[1][tid]) + (part[2][tid] + part[3][tid]);
    __syncthreads();

    if (tid < 32) {
        const int lane = tid;
        float2 v = make_float2(lg[2 * lane], lg[2 * lane + 1]);

        float m = fmaxf(v.x, v.y);
#pragma unroll
        for (int o = 16; o > 0; o >>= 1)
            m = fmaxf(m, __shfl_xor_sync(0xffffffffu, m, o));

        float e0 = expf(v.x - m);
        float e1 = expf(v.y - m);
        float ssum = e0 + e1;
#pragma unroll
        for (int o = 16; o > 0; o >>= 1)
            ssum += __shfl_xor_sync(0xffffffffu, ssum, o);

        float inv = 1.0f / ssum;
        float p0 = e0 * inv, p1 = e1 * inv;

        float* outp = out;
        float* outi = out + (size_t)NT * 8;
        float* outa = out + (size_t)NT * 16;

        *reinterpret_cast<float2*>(outa + (size_t)tok * 64 + 2 * lane)
            = make_float2(p0, p1);

        float c0 = p0, c1 = p1;
        int i0 = 2 * lane, i1 = 2 * lane + 1;
        float tv = 0.0f, tsum = 0.0f;
        int ti = 0;
#pragma unroll
        for (int r = 0; r < 8; r++) {
            float bv; int bi;
            if (c0 > c1 || (c0 == c1 && i0 < i1)) { bv = c0; bi = i0; }
            else                                  { bv = c1; bi = i1; }
#pragma unroll
            for (int o = 16; o > 0; o >>= 1) {
                float ov = __shfl_xor_sync(0xffffffffu, bv, o);
                int   oi = __shfl_xor_sync(0xffffffffu, bi, o);
                if (ov > bv || (ov == bv && oi < bi)) { bv = ov; bi = oi; }
            }
            tsum += bv;
            if (lane == r) { tv = bv; ti = bi; }
            if (bi == i0)      c0 = -1.0f;
            else if (bi == i1) c1 = -1.0f;
        }
        if (lane < 8) {
            outp[(size_t)tok * 8 + lane] = tv / (tsum + 1e-9f);
            outi[(size_t)tok * 8 + lane] = (float)ti;
        }
    }
}

extern "C" void kernel_launch(void* const* d_in, const int* in_sizes, int n_in,
                              void* d_out, int out_size)
{
    (void)in_sizes; (void)n_in; (void)out_size;
    const float* x = (const float*)d_in[0];
    const float* w = (const float*)d_in[1];
    cudaFuncSetAttribute(router_hmma, cudaFuncAttributeMaxDynamicSharedMemorySize,
                         SMEM_TOTAL);
    router_hmma<<<NT / TT, 512, SMEM_TOTAL>>>(x, w, (float*)d_out);
    router_fix<<<MAXFIX, 256>>>(x, w, (float*)d_out);
}

// round 16
// speedup vs baseline: 2.0870x; 1.2722x over previous
#include <cuda_runtime.h>
#include <cuda_fp16.h>
#include <cstdint>

#define NT    16384
#define DIM   2048
#define NE    64
#define TT    128            // tokens per CTA
#define KCH   128            // k per smem chunk
#define NCHK  (DIM / KCH)    // 16
#define KS_PER_CH 8          // k16 steps per chunk
#define NKS   (DIM / 16)     // 128 total k16 steps
#define LSTR  66
#define GAP_THRESH 1e-4f     // logit-gap flag threshold
#define MAXFIX 1024

// smem w-plane layout: [prod][ks][n][48B rows]
#define KSOFF 3104
#define POFF  (8 * KSOFF)          // 24832
#define SMEM_TOTAL (2 * POFF)      // 49664 (logits 128*66*4=33792 reused)

__device__ int g_cnt;        // flag counter (self-resetting)
__device__ int g_cnt2;       // stable snapshot for fix kernel
__device__ int g_ctas_done;  // completion ticket
__device__ int g_list[MAXFIX];

__device__ __forceinline__ uint32_t smem_u32(const void* p) {
    uint32_t a;
    asm("{ .reg .u64 t; cvta.to.shared.u64 t, %1; cvt.u32.u64 %0, t; }" : "=r"(a) : "l"(p));
    return a;
}

// split float2 into fp16 high + fp16 residual (packed half2 as u32)
__device__ __forceinline__ void split2(float2 v, uint32_t& h, uint32_t& m) {
    __half2 hh = __float22half2_rn(v);
    float2 hf = __half22float2(hh);
    __half2 mm = __floats2half2_rn(v.x - hf.x, v.y - hf.y);
    h = *reinterpret_cast<uint32_t*>(&hh);
    m = *reinterpret_cast<uint32_t*>(&mm);
}

__device__ __forceinline__ void ldm4(uint32_t addr, uint32_t& r0, uint32_t& r1,
                                     uint32_t& r2, uint32_t& r3) {
    asm volatile("ldmatrix.sync.aligned.m8n8.x4.shared.b16 {%0,%1,%2,%3}, [%4];"
                 : "=r"(r0), "=r"(r1), "=r"(r2), "=r"(r3) : "r"(addr));
}

__device__ __forceinline__ void mma16816(float* c, uint32_t a0, uint32_t a1,
                                         uint32_t a2, uint32_t a3,
                                         uint32_t b0, uint32_t b1) {
    asm volatile("mma.sync.aligned.m16n8k16.row.col.f32.f16.f16.f32 "
                 "{%0,%1,%2,%3}, {%4,%5,%6,%7}, {%8,%9}, {%0,%1,%2,%3};"
                 : "+f"(c[0]), "+f"(c[1]), "+f"(c[2]), "+f"(c[3])
                 : "r"(a0), "r"(a1), "r"(a2), "r"(a3), "r"(b0), "r"(b1));
}

// ---------------- Kernel A: HMMA fast path (unchanged, ~54us) ----------------
__global__ __launch_bounds__(512, 1)
void router_hmma(const float* __restrict__ x, const float* __restrict__ w,
                 float* __restrict__ out)
{
    extern __shared__ __align__(16) char smem[];
    const uint32_t wsu = smem_u32(smem);

    const int tid  = threadIdx.x;
    const int lane = tid & 31;
    const int wp   = tid >> 5;           // 0..15
    const int tok0 = blockIdx.x * TT;

    const int qrow  = lane >> 2;
    const int qk    = (lane & 3) * 2;
    const int rbase = 16 * (wp & 7);
    const int jb    = (wp >> 3) * 4;

    const int lm_m = lane >> 3, lm_i = lane & 7;
    const uint32_t lmoff = (uint32_t)((8 * (lm_m >> 1) + lm_i) * 48 + (lm_m & 1) * 16);

    const float* xa = x + (size_t)(tok0 + rbase + qrow) * DIM + qk;

    float acc[4][4];
#pragma unroll
    for (int j = 0; j < 4; j++)
#pragma unroll
        for (int q = 0; q < 4; q++) acc[j][q] = 0.0f;

    float2 pa[2][4];
    auto loadA = [&](int g, int s) {
        const float* p = xa + 16 * g;
        pa[s][0] = *reinterpret_cast<const float2*>(p);
        pa[s][1] = *reinterpret_cast<const float2*>(p + 8);
        pa[s][2] = *reinterpret_cast<const float2*>(p + 8 * DIM);
        pa[s][3] = *reinterpret_cast<const float2*>(p + 8 * DIM + 8);
    };
    loadA(0, 0);
    loadA(1, 1);

    float4 wr[4];
    auto loadW = [&](int ch) {
#pragma unroll
        for (int l = 0; l < 4; l++) {
            int f = tid + 512 * l;
            int n = f >> 5, q = f & 31;
            wr[l] = *reinterpret_cast<const float4*>(
                w + (size_t)n * DIM + ch * KCH + q * 4);
        }
    };
    loadW(0);

    for (int ch = 0; ch < NCHK; ch++) {
        __syncthreads();
#pragma unroll
        for (int l = 0; l < 4; l++) {
            int f = tid + 512 * l;
            int n = f >> 5, q = f & 31;
            uint32_t h01, m01, h23, m23;
            split2(make_float2(wr[l].x * 256.0f, wr[l].y * 256.0f), h01, m01);
            split2(make_float2(wr[l].z * 256.0f, wr[l].w * 256.0f), h23, m23);
            uint32_t off = (uint32_t)((q >> 2) * KSOFF + n * 48 + (q & 3) * 8);
            *reinterpret_cast<uint2*>(smem + off)        = make_uint2(h01, h23);
            *reinterpret_cast<uint2*>(smem + POFF + off) = make_uint2(m01, m23);
        }
        __syncthreads();
        if (ch + 1 < NCHK) loadW(ch + 1);

#pragma unroll
        for (int ks = 0; ks < KS_PER_CH; ks++) {
            const int g = ch * KS_PER_CH + ks;
            const int s = g & 1;

            uint32_t ah[4], am[4];
            split2(pa[s][0], ah[0], am[0]);
            split2(pa[s][2], ah[1], am[1]);
            split2(pa[s][1], ah[2], am[2]);
            split2(pa[s][3], ah[3], am[3]);
            if (g + 2 < NKS) loadA(g + 2, s);

            const uint32_t bh_base = wsu + (uint32_t)(ks * KSOFF) + lmoff;
            uint32_t bh[8], bm[8];
            ldm4(bh_base + (jb + 0) * 384, bh[0], bh[1], bh[2], bh[3]);
            ldm4(bh_base + (jb + 2) * 384, bh[4], bh[5], bh[6], bh[7]);
#pragma unroll
            for (int j = 0; j < 4; j++)
                mma16816(acc[j], ah[0], ah[1], ah[2], ah[3], bh[2 * j], bh[2 * j + 1]);
#pragma unroll
            for (int j = 0; j < 4; j++)
                mma16816(acc[j], am[0], am[1], am[2], am[3], bh[2 * j], bh[2 * j + 1]);
            ldm4(bh_base + POFF + (jb + 0) * 384, bm[0], bm[1], bm[2], bm[3]);
            ldm4(bh_base + POFF + (jb + 2) * 384, bm[4], bm[5], bm[6], bm[7]);
#pragma unroll
            for (int j = 0; j < 4; j++)
                mma16816(acc[j], ah[0], ah[1], ah[2], ah[3], bm[2 * j], bm[2 * j + 1]);
        }
    }

    __syncthreads();
    float* ls = reinterpret_cast<float*>(smem);
    {
        const int r0 = rbase + qrow, r1 = r0 + 8;
        const int e00 = 32 * (wp >> 3) + qk;
#pragma unroll
        for (int j = 0; j < 4; j++) {
            int e = e00 + 8 * j;
            *reinterpret_cast<float2*>(ls + r0 * LSTR + e) =
                make_float2(acc[j][0] * 0.00390625f, acc[j][1] * 0.00390625f);
            *reinterpret_cast<float2*>(ls + r1 * LSTR + e) =
                make_float2(acc[j][2] * 0.00390625f, acc[j][3] * 0.00390625f);
        }
    }
    __syncthreads();

    float* outp = out;
    float* outi = out + (size_t)NT * 8;
    float* outa = out + (size_t)NT * 16;

    const int tbase = wp * 8;
#pragma unroll 1
    for (int tt = 0; tt < 8; tt++) {
        const int tok = tbase + tt;
        float2 v = *reinterpret_cast<const float2*>(ls + tok * LSTR + 2 * lane);

        float m = fmaxf(v.x, v.y);
#pragma unroll
        for (int o = 16; o > 0; o >>= 1)
            m = fmaxf(m, __shfl_xor_sync(0xffffffffu, m, o));

        float e0 = expf(v.x - m);
        float e1 = expf(v.y - m);
        float ssum = e0 + e1;
#pragma unroll
        for (int o = 16; o > 0; o >>= 1)
            ssum += __shfl_xor_sync(0xffffffffu, ssum, o);

        float inv = 1.0f / ssum;
        float p0 = e0 * inv, p1 = e1 * inv;

        const int gtok = tok0 + tok;
        *reinterpret_cast<float2*>(outa + (size_t)gtok * 64 + 2 * lane)
            = make_float2(p0, p1);

        // top-9 on LOGITS, track min adjacent gap
        float c0 = v.x, c1 = v.y;
        int i0 = 2 * lane, i1 = 2 * lane + 1;
        float tv = 0.0f, tsum = 0.0f, prevv = 0.0f, mingap = 1e30f;
        int ti = 0;
#pragma unroll
        for (int r = 0; r < 9; r++) {
            float bv; int bi;
            if (c0 > c1 || (c0 == c1 && i0 < i1)) { bv = c0; bi = i0; }
            else                                  { bv = c1; bi = i1; }
#pragma unroll
            for (int o = 16; o > 0; o >>= 1) {
                float ov = __shfl_xor_sync(0xffffffffu, bv, o);
                int   oi = __shfl_xor_sync(0xffffffffu, bi, o);
                if (ov > bv || (ov == bv && oi < bi)) { bv = ov; bi = oi; }
            }
            if (r > 0) mingap = fminf(mingap, prevv - bv);
            prevv = bv;
            if (r < 8) {
                float bp = expf(bv - m) * inv;   // bitwise == winning lane's prob
                tsum += bp;
                if (lane == r) { tv = bp; ti = bi; }
                if (bi == i0)      c0 = -1e30f;
                else if (bi == i1) c1 = -1e30f;
            }
        }
        if (lane < 8) {
            outp[(size_t)gtok * 8 + lane] = tv / (tsum + 1e-9f);
            outi[(size_t)gtok * 8 + lane] = (float)ti;
        }
        if (lane == 0 && mingap < GAP_THRESH) {
            int pos = atomicAdd(&g_cnt, 1);
            if (pos < MAXFIX) g_list[pos] = gtok;
        }
    }

    // ---- counter rotation: last CTA snapshots & resets ----
    __syncthreads();
    if (tid == 0) {
        __threadfence();
        int t = atomicAdd(&g_ctas_done, 1);
        if (t == (int)gridDim.x - 1) {
            int c = atomicExch(&g_cnt, 0);
            g_cnt2 = (c > MAXFIX) ? MAXFIX : c;
            g_ctas_done = 0;
            __threadfence();
        }
    }
}

// ------- Kernel B: exact fp32 fixup, coalesced (warp-per-expert rows) -------
__global__ __launch_bounds__(256)
void router_fix(const float* __restrict__ x, const float* __restrict__ w,
                float* __restrict__ out)
{
    const int n = g_cnt2;
    if ((int)blockIdx.x >= n) return;
    const int tok = g_list[blockIdx.x];

    __shared__ __align__(16) float xsh[DIM];
    __shared__ float lg[64 + 2];

    const int tid = threadIdx.x, lane = tid & 31, wp = tid >> 5;   // 8 warps

    // stage x row (8KB), coalesced
    const float4* xr4 = reinterpret_cast<const float4*>(x + (size_t)tok * DIM);
#pragma unroll
    for (int i = 0; i < 2; i++)
        reinterpret_cast<float4*>(xsh)[tid + 256 * i] = xr4[tid + 256 * i];
    __syncthreads();

    // each warp: 8 experts, coalesced row reads, lane-partial + shuffle reduce
#pragma unroll 1
    for (int j = 0; j < 8; j++) {
        const int e = wp * 8 + j;
        const float4* wr = reinterpret_cast<const float4*>(w + (size_t)e * DIM);
        float s = 0.0f;
#pragma unroll
        for (int i = 0; i < 16; i++) {
            float4 wv = wr[lane + 32 * i];
            float4 xv = reinterpret_cast<const float4*>(xsh)[lane + 32 * i];
            s = fmaf(xv.x, wv.x, s);
            s = fmaf(xv.y, wv.y, s);
            s = fmaf(xv.z, wv.z, s);
            s = fmaf(xv.w, wv.w, s);
        }
#pragma unroll
        for (int o = 16; o > 0; o >>= 1)
            s += __shfl_xor_sync(0xffffffffu, s, o);
        if (lane == 0) lg[e] = s;
    }
    __syncthreads();

    if (tid < 32) {
        const int lane2 = tid;
        float2 v = make_float2(lg[2 * lane2], lg[2 * lane2 + 1]);

        float m = fmaxf(v.x, v.y);
#pragma unroll
        for (int o = 16; o > 0; o >>= 1)
            m = fmaxf(m, __shfl_xor_sync(0xffffffffu, m, o));

        float e0 = expf(v.x - m);
        float e1 = expf(v.y - m);
        float ssum = e0 + e1;
#pragma unroll
        for (int o = 16; o > 0; o >>= 1)
            ssum += __shfl_xor_sync(0xffffffffu, ssum, o);

        float inv = 1.0f / ssum;
        float p0 = e0 * inv, p1 = e1 * inv;

        float* outp = out;
        float* outi = out + (size_t)NT * 8;
        float* outa = out + (size_t)NT * 16;

        *reinterpret_cast<float2*>(outa + (size_t)tok * 64 + 2 * lane2)
            = make_float2(p0, p1);

        float c0 = p0, c1 = p1;
        int i0 = 2 * lane2, i1 = 2 * lane2 + 1;
        float tv = 0.0f, tsum = 0.0f;
        int ti = 0;
#pragma unroll
        for (int r = 0; r < 8; r++) {
            float bv; int bi;
            if (c0 > c1 || (c0 == c1 && i0 < i1)) { bv = c0; bi = i0; }
            else                                  { bv = c1; bi = i1; }
#pragma unroll
            for (int o = 16; o > 0; o >>= 1) {
                float ov = __shfl_xor_sync(0xffffffffu, bv, o);
                int   oi = __shfl_xor_sync(0xffffffffu, bi, o);
                if (ov > bv || (ov == bv && oi < bi)) { bv = ov; bi = oi; }
            }
            tsum += bv;
            if (lane2 == r) { tv = bv; ti = bi; }
            if (bi == i0)      c0 = -1.0f;
            else if (bi == i1) c1 = -1.0f;
        }
        if (lane2 < 8) {
            outp[(size_t)tok * 8 + lane2] = tv / (tsum + 1e-9f);
            outi[(size_t)tok * 8 + lane2] = (float)ti;
        }
    }
}

extern "C" void kernel_launch(void* const* d_in, const int* in_sizes, int n_in,
                              void* d_out, int out_size)
{
    (void)in_sizes; (void)n_in; (void)out_size;
    const float* x = (const float*)d_in[0];
    const float* w = (const float*)d_in[1];
    cudaFuncSetAttribute(router_hmma, cudaFuncAttributeMaxDynamicSharedMemorySize,
                         SMEM_TOTAL);
    router_hmma<<<NT / TT, 512, SMEM_TOTAL>>>(x, w, (float*)d_out);
    router_fix<<<MAXFIX, 256>>>(x, w, (float*)d_out);
}

// round 17
// speedup vs baseline: 2.1724x; 1.0409x over previous
#include <cuda_runtime.h>
#include <cuda_fp16.h>
#include <cstdint>

#define NT    16384
#define DIM   2048
#define NE    64
#define TT    64             // tokens per CTA (2 CTAs/SM)
#define KCH   128            // k per smem chunk
#define NCHK  (DIM / KCH)    // 16
#define KS_PER_CH 8
#define NKS   (DIM / 16)     // 128
#define LSTR  66
#define GAP_THRESH 1e-4f
#define MAXFIX 1024

// smem w-plane layout (R4 exact): [prod][ks][n][48B rows]
#define KSOFF 3104
#define POFF  (8 * KSOFF)          // 24832
#define SMEM_TOTAL (2 * POFF)      // 49664 (logits 64*66*4=16896 reused)

__device__ int g_cnt;
__device__ int g_cnt2;
__device__ int g_ctas_done;
__device__ int g_list[MAXFIX];

// pre-split w in staging order: [ch(16)][t(2048)] x uint4{h01,h23,m01,m23}
__device__ __align__(16) uint4 g_w[NCHK * 2048];   // 512 KB

__device__ __forceinline__ uint32_t smem_u32(const void* p) {
    uint32_t a;
    asm("{ .reg .u64 t; cvta.to.shared.u64 t, %1; cvt.u32.u64 %0, t; }" : "=r"(a) : "l"(p));
    return a;
}
__device__ __forceinline__ void split2(float2 v, uint32_t& h, uint32_t& m) {
    __half2 hh = __float22half2_rn(v);
    float2 hf = __half22float2(hh);
    __half2 mm = __floats2half2_rn(v.x - hf.x, v.y - hf.y);
    h = *reinterpret_cast<uint32_t*>(&hh);
    m = *reinterpret_cast<uint32_t*>(&mm);
}
__device__ __forceinline__ void ldm4(uint32_t addr, uint32_t& r0, uint32_t& r1,
                                     uint32_t& r2, uint32_t& r3) {
    asm volatile("ldmatrix.sync.aligned.m8n8.x4.shared.b16 {%0,%1,%2,%3}, [%4];"
                 : "=r"(r0), "=r"(r1), "=r"(r2), "=r"(r3) : "r"(addr));
}
__device__ __forceinline__ void mma16816(float* c, uint32_t a0, uint32_t a1,
                                         uint32_t a2, uint32_t a3,
                                         uint32_t b0, uint32_t b1) {
    asm volatile("mma.sync.aligned.m16n8k16.row.col.f32.f16.f16.f32 "
                 "{%0,%1,%2,%3}, {%4,%5,%6,%7}, {%8,%9}, {%0,%1,%2,%3};"
                 : "+f"(c[0]), "+f"(c[1]), "+f"(c[2]), "+f"(c[3])
                 : "r"(a0), "r"(a1), "r"(a2), "r"(a3), "r"(b0), "r"(b1));
}

// ---- prep: w (x256) -> fp16 h/m, staging order ----
__global__ __launch_bounds__(256) void prep_wf(const float* __restrict__ w) {
    const int idx = blockIdx.x * 256 + threadIdx.x;   // 32768 = 16ch x 2048t
    const int ch = idx >> 11, t = idx & 2047;
    const int n = t >> 5, q = t & 31;
    float4 v = *reinterpret_cast<const float4*>(w + (size_t)n * DIM + ch * KCH + q * 4);
    uint32_t h01, m01, h23, m23;
    split2(make_float2(v.x * 256.0f, v.y * 256.0f), h01, m01);
    split2(make_float2(v.z * 256.0f, v.w * 256.0f), h23, m23);
    g_w[idx] = make_uint4(h01, h23, m01, m23);
}

// ---------------- Kernel A: HMMA fast path (R4 loop, TT=64, occ 2) ----------------
__global__ __launch_bounds__(256, 2)
void router_hmma(const float* __restrict__ x, const float* __restrict__ w,
                 float* __restrict__ out)
{
    extern __shared__ __align__(16) char smem[];
    const uint32_t wsu = smem_u32(smem);

    const int tid  = threadIdx.x;
    const int lane = tid & 31;
    const int wp   = tid >> 5;           // 0..7
    const int tok0 = blockIdx.x * TT;

    const int qrow  = lane >> 2;
    const int qk    = (lane & 3) * 2;
    const int rbase = 16 * (wp & 3);     // 4 token groups
    const int jb    = (wp >> 2) * 4;     // 2 expert halves

    const int lm_m = lane >> 3, lm_i = lane & 7;
    const uint32_t lmoff = (uint32_t)((8 * (lm_m >> 1) + lm_i) * 48 + (lm_m & 1) * 16);

    const float* xa = x + (size_t)(tok0 + rbase + qrow) * DIM + qk;

    float acc[4][4];
#pragma unroll
    for (int j = 0; j < 4; j++)
#pragma unroll
        for (int q = 0; q < 4; q++) acc[j][q] = 0.0f;

    float2 pa[2][4];
    auto loadA = [&](int g, int s) {
        const float* p = xa + 16 * g;
        pa[s][0] = *reinterpret_cast<const float2*>(p);
        pa[s][1] = *reinterpret_cast<const float2*>(p + 8);
        pa[s][2] = *reinterpret_cast<const float2*>(p + 8 * DIM);
        pa[s][3] = *reinterpret_cast<const float2*>(p + 8 * DIM + 8);
    };
    loadA(0, 0);
    loadA(1, 1);

    uint4 wr[8];
    auto loadW = [&](int ch) {
#pragma unroll
        for (int l = 0; l < 8; l++)
            wr[l] = g_w[ch * 2048 + tid + 256 * l];
    };
    loadW(0);

    for (int ch = 0; ch < NCHK; ch++) {
        __syncthreads();    // previous compute done -> image free
#pragma unroll
        for (int l = 0; l < 8; l++) {
            int f = tid + 256 * l;
            int n = f >> 5, q = f & 31;
            uint32_t off = (uint32_t)((q >> 2) * KSOFF + n * 48 + (q & 3) * 8);
            *reinterpret_cast<uint2*>(smem + off)        = make_uint2(wr[l].x, wr[l].y);
            *reinterpret_cast<uint2*>(smem + POFF + off) = make_uint2(wr[l].z, wr[l].w);
        }
        __syncthreads();
        if (ch + 1 < NCHK) loadW(ch + 1);

#pragma unroll
        for (int ks = 0; ks < KS_PER_CH; ks++) {
            const int g = ch * KS_PER_CH + ks;
            const int s = g & 1;

            uint32_t ah[4], am[4];
            split2(pa[s][0], ah[0], am[0]);
            split2(pa[s][2], ah[1], am[1]);
            split2(pa[s][1], ah[2], am[2]);
            split2(pa[s][3], ah[3], am[3]);
            if (g + 2 < NKS) loadA(g + 2, s);

            const uint32_t bh_base = wsu + (uint32_t)(ks * KSOFF) + lmoff;
            uint32_t bh[8], bm[8];
            ldm4(bh_base + (jb + 0) * 384, bh[0], bh[1], bh[2], bh[3]);
            ldm4(bh_base + (jb + 2) * 384, bh[4], bh[5], bh[6], bh[7]);
#pragma unroll
            for (int j = 0; j < 4; j++)
                mma16816(acc[j], ah[0], ah[1], ah[2], ah[3], bh[2 * j], bh[2 * j + 1]);
#pragma unroll
            for (int j = 0; j < 4; j++)
                mma16816(acc[j], am[0], am[1], am[2], am[3], bh[2 * j], bh[2 * j + 1]);
            ldm4(bh_base + POFF + (jb + 0) * 384, bm[0], bm[1], bm[2], bm[3]);
            ldm4(bh_base + POFF + (jb + 2) * 384, bm[4], bm[5], bm[6], bm[7]);
#pragma unroll
            for (int j = 0; j < 4; j++)
                mma16816(acc[j], ah[0], ah[1], ah[2], ah[3], bm[2 * j], bm[2 * j + 1]);
        }
    }

    __syncthreads();
    float* ls = reinterpret_cast<float*>(smem);
    {
        const int r0 = rbase + qrow, r1 = r0 + 8;
        const int e00 = 32 * (wp >> 2) + qk;
#pragma unroll
        for (int j = 0; j < 4; j++) {
            int e = e00 + 8 * j;
            *reinterpret_cast<float2*>(ls + r0 * LSTR + e) =
                make_float2(acc[j][0] * 0.00390625f, acc[j][1] * 0.00390625f);
            *reinterpret_cast<float2*>(ls + r1 * LSTR + e) =
                make_float2(acc[j][2] * 0.00390625f, acc[j][3] * 0.00390625f);
        }
    }
    __syncthreads();

    float* outp = out;
    float* outi = out + (size_t)NT * 8;
    float* outa = out + (size_t)NT * 16;

    const int tbase = wp * 8;
#pragma unroll 1
    for (int tt = 0; tt < 8; tt++) {
        const int tok = tbase + tt;
        float2 v = *reinterpret_cast<const float2*>(ls + tok * LSTR + 2 * lane);

        float m = fmaxf(v.x, v.y);
#pragma unroll
        for (int o = 16; o > 0; o >>= 1)
            m = fmaxf(m, __shfl_xor_sync(0xffffffffu, m, o));

        float e0 = expf(v.x - m);
        float e1 = expf(v.y - m);
        float ssum = e0 + e1;
#pragma unroll
        for (int o = 16; o > 0; o >>= 1)
            ssum += __shfl_xor_sync(0xffffffffu, ssum, o);

        float inv = 1.0f / ssum;
        float p0 = e0 * inv, p1 = e1 * inv;

        const int gtok = tok0 + tok;
        *reinterpret_cast<float2*>(outa + (size_t)gtok * 64 + 2 * lane)
            = make_float2(p0, p1);

        // top-9 on LOGITS, min adjacent gap -> flag near-ties
        float c0 = v.x, c1 = v.y;
        int i0 = 2 * lane, i1 = 2 * lane + 1;
        float tv = 0.0f, tsum = 0.0f, prevv = 0.0f, mingap = 1e30f;
        int ti = 0;
#pragma unroll
        for (int r = 0; r < 9; r++) {
            float bv; int bi;
            if (c0 > c1 || (c0 == c1 && i0 < i1)) { bv = c0; bi = i0; }
            else                                  { bv = c1; bi = i1; }
#pragma unroll
            for (int o = 16; o > 0; o >>= 1) {
                float ov = __shfl_xor_sync(0xffffffffu, bv, o);
                int   oi = __shfl_xor_sync(0xffffffffu, bi, o);
                if (ov > bv || (ov == bv && oi < bi)) { bv = ov; bi = oi; }
            }
            if (r > 0) mingap = fminf(mingap, prevv - bv);
            prevv = bv;
            if (r < 8) {
                float bp = expf(bv - m) * inv;
                tsum += bp;
                if (lane == r) { tv = bp; ti = bi; }
                if (bi == i0)      c0 = -1e30f;
                else if (bi == i1) c1 = -1e30f;
            }
        }
        if (lane < 8) {
            outp[(size_t)gtok * 8 + lane] = tv / (tsum + 1e-9f);
            outi[(size_t)gtok * 8 + lane] = (float)ti;
        }
        if (lane == 0 && mingap < GAP_THRESH) {
            int pos = atomicAdd(&g_cnt, 1);
            if (pos < MAXFIX) g_list[pos] = gtok;
        }
    }

    // ---- counter rotation: last CTA snapshots & resets ----
    __syncthreads();
    if (tid == 0) {
        __threadfence();
        int t = atomicAdd(&g_ctas_done, 1);
        if (t == (int)gridDim.x - 1) {
            int c = atomicExch(&g_cnt, 0);
            g_cnt2 = (c > MAXFIX) ? MAXFIX : c;
            g_ctas_done = 0;
            __threadfence();
        }
    }
}

// ------- Kernel B: exact fp32 fixup, coalesced (warp-per-expert rows) -------
__global__ __launch_bounds__(256)
void router_fix(const float* __restrict__ x, const float* __restrict__ w,
                float* __restrict__ out)
{
    const int n = g_cnt2;
    if ((int)blockIdx.x >= n) return;
    const int tok = g_list[blockIdx.x];

    __shared__ __align__(16) float xsh[DIM];
    __shared__ float lg[64 + 2];

    const int tid = threadIdx.x, lane = tid & 31, wp = tid >> 5;

    const float4* xr4 = reinterpret_cast<const float4*>(x + (size_t)tok * DIM);
#pragma unroll
    for (int i = 0; i < 2; i++)
        reinterpret_cast<float4*>(xsh)[tid + 256 * i] = xr4[tid + 256 * i];
    __syncthreads();

#pragma unroll 1
    for (int j = 0; j < 8; j++) {
        const int e = wp * 8 + j;
        const float4* wr = reinterpret_cast<const float4*>(w + (size_t)e * DIM);
        float s = 0.0f;
#pragma unroll
        for (int i = 0; i < 16; i++) {
            float4 wv = wr[lane + 32 * i];
            float4 xv = reinterpret_cast<const float4*>(xsh)[lane + 32 * i];
            s = fmaf(xv.x, wv.x, s);
            s = fmaf(xv.y, wv.y, s);
            s = fmaf(xv.z, wv.z, s);
            s = fmaf(xv.w, wv.w, s);
        }
#pragma unroll
        for (int o = 16; o > 0; o >>= 1)
            s += __shfl_xor_sync(0xffffffffu, s, o);
        if (lane == 0) lg[e] = s;
    }
    __syncthreads();

    if (tid < 32) {
        const int lane2 = tid;
        float2 v = make_float2(lg[2 * lane2], lg[2 * lane2 + 1]);

        float m = fmaxf(v.x, v.y);
#pragma unroll
        for (int o = 16; o > 0; o >>= 1)
            m = fmaxf(m, __shfl_xor_sync(0xffffffffu, m, o));

        float e0 = expf(v.x - m);
        float e1 = expf(v.y - m);
        float ssum = e0 + e1;
#pragma unroll
        for (int o = 16; o > 0; o >>= 1)
            ssum += __shfl_xor_sync(0xffffffffu, ssum, o);

        float inv = 1.0f / ssum;
        float p0 = e0 * inv, p1 = e1 * inv;

        float* outp = out;
        float* outi = out + (size_t)NT * 8;
        float* outa = out + (size_t)NT * 16;

        *reinterpret_cast<float2*>(outa + (size_t)tok * 64 + 2 * lane2)
            = make_float2(p0, p1);

        float c0 = p0, c1 = p1;
        int i0 = 2 * lane2, i1 = 2 * lane2 + 1;
        float tv = 0.0f, tsum = 0.0f;
        int ti = 0;
#pragma unroll
        for (int r = 0; r < 8; r++) {
            float bv; int bi;
            if (c0 > c1 || (c0 == c1 && i0 < i1)) { bv = c0; bi = i0; }
            else                                  { bv = c1; bi = i1; }
#pragma unroll
            for (int o = 16; o > 0; o >>= 1) {
                float ov = __shfl_xor_sync(0xffffffffu, bv, o);
                int   oi = __shfl_xor_sync(0xffffffffu, bi, o);
                if (ov > bv || (ov == bv && oi < bi)) { bv = ov; bi = oi; }
            }
            tsum += bv;
            if (lane2 == r) { tv = bv; ti = bi; }
            if (bi == i0)      c0 = -1.0f;
            else if (bi == i1) c1 = -1.0f;
        }
        if (lane2 < 8) {
            outp[(size_t)tok * 8 + lane2] = tv / (tsum + 1e-9f);
            outi[(size_t)tok * 8 + lane2] = (float)ti;
        }
    }
}

extern "C" void kernel_launch(void* const* d_in, const int* in_sizes, int n_in,
                              void* d_out, int out_size)
{
    (void)in_sizes; (void)n_in; (void)out_size;
    const float* x = (const float*)d_in[0];
    const float* w = (const float*)d_in[1];
    cudaFuncSetAttribute(router_hmma, cudaFuncAttributeMaxDynamicSharedMemorySize,
                         SMEM_TOTAL);
    prep_wf<<<128, 256>>>(w);
    router_hmma<<<NT / TT, 256, SMEM_TOTAL>>>(x, w, (float*)d_out);
    router_fix<<<MAXFIX, 256>>>(x, w, (float*)d_out);
}